// round 3
// baseline (speedup 1.0000x reference)
#include <cuda_runtime.h>
#include <cuda_bf16.h>
#include <math.h>

// Problem shape (fixed for this problem instance)
#define B_   4
#define NA   8192
#define NB_  8192
#define D_   256
#define TOPK 8

// ---------------------------------------------------------------------------
// Scratch (static device globals; no dynamic allocation allowed)
// ---------------------------------------------------------------------------
__device__ float g_P[B_ * NA * D_];        // af @ W1b^T + b1      [32768,256]
__device__ float g_Q[B_ * NB_ * D_];       // bf @ (W1a-W1b)^T     [32768,256]
__device__ float g_S[B_ * NA * D_];        // sum_k relu(Q+P)*dw   [32768,256]
__device__ float g_WdT[D_ * D_];           // (W1a-W1b)^T  [c,d]
__device__ float g_W1bT[D_ * D_];          // W1b^T        [c,d]
__device__ float g_W2T[D_ * D_];           // W2^T         [d,e]
__device__ int   g_idx[B_ * NA * TOPK];
__device__ float g_dw[B_ * NA * TOPK];

// ---------------------------------------------------------------------------
// Weight preprocessing: build transposed / differenced weight matrices
//   WdT[c,d]  = w1[d,c] - w1[d,256+c]
//   W1bT[c,d] = w1[d,256+c]
//   W2T[d,e]  = w2[e,d]
// grid 256 blocks x 256 threads; writes coalesced.
// ---------------------------------------------------------------------------
__global__ void prep_w_kernel(const float* __restrict__ w1,
                              const float* __restrict__ w2,
                              float* __restrict__ WdT,
                              float* __restrict__ W1bT,
                              float* __restrict__ W2T) {
    int i = blockIdx.x;   // c for WdT/W1bT, d for W2T
    int t = threadIdx.x;  // d for WdT/W1bT, e for W2T
    float a = w1[t * 512 + i];
    float b = w1[t * 512 + 256 + i];
    WdT[i * 256 + t]  = a - b;
    W1bT[i * 256 + t] = b;
    W2T[i * 256 + t]  = w2[t * 256 + i];
}

// ---------------------------------------------------------------------------
// kNN top-8 (exact, with jax top_k lower-index tie-breaking).
// One warp per query point. Candidate coords packed (x|y<<8|z<<16) in smem.
// key = (d2 << 13) | j  -> 8 smallest keys == 8 nearest, ties by lower index.
// ---------------------------------------------------------------------------
__global__ void knn_kernel(const int* __restrict__ coords_a,
                           const int* __restrict__ coords_b,
                           int* __restrict__ idx_out,
                           float* __restrict__ dw_out) {
    __shared__ unsigned cbp[NB_];   // 32 KB
    const int b = blockIdx.y;
    const int* cb = coords_b + (size_t)b * NB_ * 3;
    for (int i = threadIdx.x; i < NB_; i += blockDim.x) {
        unsigned x = ((unsigned)cb[i * 3 + 0]) >> 4;
        unsigned y = ((unsigned)cb[i * 3 + 1]) >> 4;
        unsigned z = ((unsigned)cb[i * 3 + 2]) >> 4;
        cbp[i] = x | (y << 8) | (z << 16);
    }
    __syncthreads();

    const int warp = threadIdx.x >> 5;
    const int lane = threadIdx.x & 31;
    const int n = blockIdx.x * 8 + warp;

    const int* ca = coords_a + ((size_t)b * NA + n) * 3;
    const int qx = ca[0] >> 4, qy = ca[1] >> 4, qz = ca[2] >> 4;

    unsigned best[8];
#pragma unroll
    for (int t = 0; t < 8; ++t) best[t] = 0xFFFFFFFFu;

    // Each lane scans candidates lane, lane+32, ... (conflict-free smem)
    for (int j0 = 0; j0 < NB_; j0 += 32) {
        const int j = j0 + lane;
        const unsigned p = cbp[j];
        const int dx = (int)(p & 255u) - qx;
        const int dy = (int)((p >> 8) & 255u) - qy;
        const int dz = (int)(p >> 16) - qz;
        const unsigned d2 = (unsigned)(dx * dx + dy * dy + dz * dz);
        const unsigned key = (d2 << 13) | (unsigned)j;
        if (key < best[7]) {
            best[7] = key;
#pragma unroll
            for (int t = 7; t > 0; --t) {
                unsigned lo = min(best[t - 1], best[t]);
                unsigned hi = max(best[t - 1], best[t]);
                best[t - 1] = lo;
                best[t]     = hi;
            }
        }
    }

    // Warp merge: 8 rounds of reduce-min; popping lane shifts its list down.
    unsigned sel = 0;
#pragma unroll
    for (int r = 0; r < 8; ++r) {
        const unsigned v = best[0];
        const unsigned m = __reduce_min_sync(0xFFFFFFFFu, v);
        if (lane == r) sel = m;
        if (v == m) {
#pragma unroll
            for (int t = 0; t < 7; ++t) best[t] = best[t + 1];
            best[7] = 0xFFFFFFFFu;
        }
    }

    if (lane < 8) {
        const int j = (int)(sel & 8191u);
        const float dist = sqrtf((float)(sel >> 13)) * (1.0f / 128.0f);
        const float dw = 0.5f - fminf(dist, 0.5f);
        const size_t o = ((size_t)b * NA + n) * 8 + lane;
        idx_out[o] = j;
        dw_out[o]  = dw;
    }
}

// ---------------------------------------------------------------------------
// fp32 SGEMM: C[M,256] = A[M,256] @ B[256,256]  (+ bscale * bias broadcast)
// BM=BN=128, BK=8, 256 threads, 8x8 per thread. M multiple of 128, no bounds.
// ldc allows strided writes directly into the concatenated output tensor.
// ---------------------------------------------------------------------------
__global__ __launch_bounds__(256, 2)
void sgemm_kernel(const float* __restrict__ A, const float* __restrict__ Bm,
                  float* __restrict__ C, int ldc,
                  const float* __restrict__ bias, float bscale) {
    const int K = 256;
    __shared__ float As[8][128];
    __shared__ float Bs[8][128];

    const int tid  = threadIdx.x;
    const int tx   = tid & 15;          // 16 thread-cols
    const int ty   = tid >> 4;          // 16 thread-rows
    const int arow = tid >> 1;          // A tile loader: row 0..127
    const int acol = (tid & 1) << 2;    // col {0,4}
    const int brow = tid >> 5;          // B tile loader: row 0..7
    const int bcol = (tid & 31) << 2;   // col {0,4,...,124}

    const float* Ap = A + (size_t)blockIdx.y * 128 * K;
    const float* Bp = Bm + blockIdx.x * 128;

    float acc[8][8];
#pragma unroll
    for (int i = 0; i < 8; ++i)
#pragma unroll
        for (int j = 0; j < 8; ++j) acc[i][j] = 0.f;

    for (int k0 = 0; k0 < K; k0 += 8) {
        float4 av = *(const float4*)(Ap + (size_t)arow * K + k0 + acol);
        As[acol + 0][arow] = av.x;
        As[acol + 1][arow] = av.y;
        As[acol + 2][arow] = av.z;
        As[acol + 3][arow] = av.w;
        *(float4*)(&Bs[brow][bcol]) = *(const float4*)(Bp + (size_t)(k0 + brow) * 256 + bcol);
        __syncthreads();

#pragma unroll
        for (int kk = 0; kk < 8; ++kk) {
            float ar[8], br[8];
            *(float4*)(ar)     = *(const float4*)(&As[kk][ty * 8]);
            *(float4*)(ar + 4) = *(const float4*)(&As[kk][ty * 8 + 4]);
            *(float4*)(br)     = *(const float4*)(&Bs[kk][tx * 8]);
            *(float4*)(br + 4) = *(const float4*)(&Bs[kk][tx * 8 + 4]);
#pragma unroll
            for (int i = 0; i < 8; ++i)
#pragma unroll
                for (int j = 0; j < 8; ++j)
                    acc[i][j] += ar[i] * br[j];
        }
        __syncthreads();
    }

    const int crow = blockIdx.y * 128 + ty * 8;
    const int ccol = blockIdx.x * 128 + tx * 8;
    float bb[8];
#pragma unroll
    for (int j = 0; j < 8; ++j) bb[j] = bias ? bias[ccol + j] * bscale : 0.f;

#pragma unroll
    for (int i = 0; i < 8; ++i) {
        float4 v0 = make_float4(acc[i][0] + bb[0], acc[i][1] + bb[1],
                                acc[i][2] + bb[2], acc[i][3] + bb[3]);
        float4 v1 = make_float4(acc[i][4] + bb[4], acc[i][5] + bb[5],
                                acc[i][6] + bb[6], acc[i][7] + bb[7]);
        float* cp = C + (size_t)(crow + i) * ldc + ccol;
        *(float4*)(cp)     = v0;
        *(float4*)(cp + 4) = v1;
    }
}

// ---------------------------------------------------------------------------
// Gather-reduce: S[q,:] = sum_k relu(Q[b,idx_k,:] + P[q,:]) * dw_k
// 64 threads per query (4 floats each, float4), 4 queries per 256-thread block.
// ---------------------------------------------------------------------------
__global__ void gather_reduce_kernel(const float* __restrict__ P,
                                     const float* __restrict__ Q,
                                     const int* __restrict__ idx,
                                     const float* __restrict__ dw,
                                     float* __restrict__ S) {
    const int tid = threadIdx.x;
    const int q = blockIdx.x * 4 + (tid >> 6);
    const int l = tid & 63;
    const int b = q >> 13;  // q / 8192

    const float4* P4 = (const float4*)P;
    const float4* Q4 = (const float4*)Q + (size_t)b * NB_ * 64;

    const float4 p = P4[(size_t)q * 64 + l];
    float4 acc = make_float4(0.f, 0.f, 0.f, 0.f);

#pragma unroll
    for (int k = 0; k < 8; ++k) {
        const int   j = idx[(size_t)q * 8 + k];
        const float w = dw[(size_t)q * 8 + k];
        const float4 v = Q4[(size_t)j * 64 + l];
        acc.x += fmaxf(v.x + p.x, 0.f) * w;
        acc.y += fmaxf(v.y + p.y, 0.f) * w;
        acc.z += fmaxf(v.z + p.z, 0.f) * w;
        acc.w += fmaxf(v.w + p.w, 0.f) * w;
    }
    ((float4*)S)[(size_t)q * 64 + l] = acc;
}

// ---------------------------------------------------------------------------
// Copy a_feats into out[..., 0:256] (out is [B, Na, 512])
// ---------------------------------------------------------------------------
__global__ void copy_a_kernel(const float4* __restrict__ af4, float4* __restrict__ out4) {
    const int i = blockIdx.x * blockDim.x + threadIdx.x;  // over B*NA*64
    const int m = i >> 6;
    const int c = i & 63;
    out4[(size_t)m * 128 + c] = af4[i];
}

// ---------------------------------------------------------------------------
extern "C" void kernel_launch(void* const* d_in, const int* in_sizes, int n_in,
                              void* d_out, int out_size) {
    const float* af = (const float*)d_in[0];
    const float* bf = (const float*)d_in[1];
    const int*   ca = (const int*)d_in[2];
    const int*   cb = (const int*)d_in[3];
    const float* w1 = (const float*)d_in[4];
    const float* b1 = (const float*)d_in[5];
    const float* w2 = (const float*)d_in[6];
    const float* b2 = (const float*)d_in[7];
    float* out = (float*)d_out;

    float *P, *Q, *S, *WdT, *W1bT, *W2T, *dw;
    int* idx;
    cudaGetSymbolAddress((void**)&P,    g_P);
    cudaGetSymbolAddress((void**)&Q,    g_Q);
    cudaGetSymbolAddress((void**)&S,    g_S);
    cudaGetSymbolAddress((void**)&WdT,  g_WdT);
    cudaGetSymbolAddress((void**)&W1bT, g_W1bT);
    cudaGetSymbolAddress((void**)&W2T,  g_W2T);
    cudaGetSymbolAddress((void**)&idx,  g_idx);
    cudaGetSymbolAddress((void**)&dw,   g_dw);

    // 1. Weight prep (tiny)
    prep_w_kernel<<<256, 256>>>(w1, w2, WdT, W1bT, W2T);

    // 2. Exact top-8 kNN (one warp per query)
    knn_kernel<<<dim3(NA / 8, B_), 256>>>(ca, cb, idx, dw);

    // 3. P = af @ W1b^T + b1   [32768, 256]
    sgemm_kernel<<<dim3(2, (B_ * NA) / 128), 256>>>(af, W1bT, P, 256, b1, 1.f);

    // 4. Q = bf @ (W1a - W1b)^T  [32768, 256]
    sgemm_kernel<<<dim3(2, (B_ * NB_) / 128), 256>>>(bf, WdT, Q, 256, (const float*)nullptr, 0.f);

    // 5. S = sum_k relu(Q[idx_k] + P) * dw_k
    gather_reduce_kernel<<<(B_ * NA) / 4, 256>>>(P, Q, idx, dw, S);

    // 6. out[..., 256:512] = S @ W2^T + 8*b2   (strided epilogue, ldc=512)
    sgemm_kernel<<<dim3(2, (B_ * NA) / 128), 256>>>(S, W2T, out + 256, 512, b2, 8.f);

    // 7. out[..., 0:256] = a_feats
    copy_a_kernel<<<(B_ * NA * D_ / 4) / 256, 256>>>((const float4*)af, (float4*)out);
}

// round 4
// speedup vs baseline: 1.0818x; 1.0818x over previous
#include <cuda_runtime.h>
#include <cuda_bf16.h>
#include <math.h>

// Problem shape (fixed for this problem instance)
#define B_   4
#define NA   8192
#define NB_  8192
#define D_   256
#define TOPK 8

// ---------------------------------------------------------------------------
// Scratch (static device globals; no dynamic allocation allowed)
// ---------------------------------------------------------------------------
__device__ float g_P[B_ * NA * D_];        // af @ W1b^T + b1      [32768,256]
__device__ float g_Q[B_ * NB_ * D_];       // bf @ (W1a-W1b)^T     [32768,256]
__device__ float g_S[B_ * NA * D_];        // sum_k relu(Q+P)*dw   [32768,256]
__device__ float g_WdT[D_ * D_];           // (W1a-W1b)^T  [c,d]
__device__ float g_W1bT[D_ * D_];          // W1b^T        [c,d]
__device__ float g_W2T[D_ * D_];           // W2^T         [d,e]
__device__ int   g_idx[B_ * NA * TOPK];
__device__ float g_dw[B_ * NA * TOPK];

// ---------------------------------------------------------------------------
// Weight preprocessing
// ---------------------------------------------------------------------------
__global__ void prep_w_kernel(const float* __restrict__ w1,
                              const float* __restrict__ w2,
                              float* __restrict__ WdT,
                              float* __restrict__ W1bT,
                              float* __restrict__ W2T) {
    int i = blockIdx.x;
    int t = threadIdx.x;
    float a = w1[t * 512 + i];
    float b = w1[t * 512 + 256 + i];
    WdT[i * 256 + t]  = a - b;
    W1bT[i * 256 + t] = b;
    W2T[i * 256 + t]  = w2[t * 256 + i];
}

// ---------------------------------------------------------------------------
// kNN top-8 (exact, with jax top_k lower-index tie-breaking).
// One warp per query. d2 via SIMD: vabsdiffu4 + dp4a (diffs <= 127 fit s8).
// key = (d2 << 13) | j  -> 8 smallest keys == 8 nearest, ties by lower index.
// ---------------------------------------------------------------------------
__global__ void knn_kernel(const int* __restrict__ coords_a,
                           const int* __restrict__ coords_b,
                           int* __restrict__ idx_out,
                           float* __restrict__ dw_out) {
    __shared__ unsigned cbp[NB_];   // 32 KB
    const int b = blockIdx.y;
    const int* cb = coords_b + (size_t)b * NB_ * 3;
    for (int i = threadIdx.x; i < NB_; i += blockDim.x) {
        unsigned x = ((unsigned)cb[i * 3 + 0]) >> 4;
        unsigned y = ((unsigned)cb[i * 3 + 1]) >> 4;
        unsigned z = ((unsigned)cb[i * 3 + 2]) >> 4;
        cbp[i] = x | (y << 8) | (z << 16);
    }
    __syncthreads();

    const int warp = threadIdx.x >> 5;
    const int lane = threadIdx.x & 31;
    const int n = blockIdx.x * 8 + warp;

    const int* ca = coords_a + ((size_t)b * NA + n) * 3;
    const unsigned qx = ((unsigned)ca[0]) >> 4;
    const unsigned qy = ((unsigned)ca[1]) >> 4;
    const unsigned qz = ((unsigned)ca[2]) >> 4;
    const unsigned qp = qx | (qy << 8) | (qz << 16);

    unsigned best[8];
#pragma unroll
    for (int t = 0; t < 8; ++t) best[t] = 0xFFFFFFFFu;

    for (int j0 = 0; j0 < NB_; j0 += 32) {
        const int j = j0 + lane;
        const unsigned p = cbp[j];
        const unsigned ad = __vabsdiffu4(p, qp);     // |dx|,|dy|,|dz|,0 bytes
        const unsigned d2 = (unsigned)__dp4a((int)ad, (int)ad, 0);
        const unsigned key = (d2 << 13) | (unsigned)j;
        if (key < best[7]) {
            best[7] = key;
#pragma unroll
            for (int t = 7; t > 0; --t) {
                unsigned lo = min(best[t - 1], best[t]);
                unsigned hi = max(best[t - 1], best[t]);
                best[t - 1] = lo;
                best[t]     = hi;
            }
        }
    }

    unsigned sel = 0;
#pragma unroll
    for (int r = 0; r < 8; ++r) {
        const unsigned v = best[0];
        const unsigned m = __reduce_min_sync(0xFFFFFFFFu, v);
        if (lane == r) sel = m;
        if (v == m) {
#pragma unroll
            for (int t = 0; t < 7; ++t) best[t] = best[t + 1];
            best[7] = 0xFFFFFFFFu;
        }
    }

    if (lane < 8) {
        const int j = (int)(sel & 8191u);
        const float dist = sqrtf((float)(sel >> 13)) * (1.0f / 128.0f);
        const float dw = 0.5f - fminf(dist, 0.5f);
        const size_t o = ((size_t)b * NA + n) * 8 + lane;
        idx_out[o] = j;
        dw_out[o]  = dw;
    }
}

// ---------------------------------------------------------------------------
// TF32 tensor-core GEMM: C[M,256] = A[M,256] @ B[256,256] (+ bscale*bias)
// BM=BN=128, BK=16, 256 threads, 8 warps as 2x4 (warp tile 64x32).
// mma.sync.aligned.m16n8k8.row.col.f32.tf32.tf32.f32
// Smem: As [128][20] row-major (pad 4 -> conflict-free frag reads),
//       Bs [16][136] k-major  (pad 8 -> conflict-free frag reads).
// ---------------------------------------------------------------------------
__device__ __forceinline__ uint4 cvt_tf32x4(float4 v) {
    uint4 r;
    asm("cvt.rna.tf32.f32 %0, %1;" : "=r"(r.x) : "f"(v.x));
    asm("cvt.rna.tf32.f32 %0, %1;" : "=r"(r.y) : "f"(v.y));
    asm("cvt.rna.tf32.f32 %0, %1;" : "=r"(r.z) : "f"(v.z));
    asm("cvt.rna.tf32.f32 %0, %1;" : "=r"(r.w) : "f"(v.w));
    return r;
}

__device__ __forceinline__ void mma_tf32(float* c,
                                         unsigned a0, unsigned a1, unsigned a2, unsigned a3,
                                         unsigned b0, unsigned b1) {
    asm volatile(
        "mma.sync.aligned.m16n8k8.row.col.f32.tf32.tf32.f32 "
        "{%0,%1,%2,%3}, {%4,%5,%6,%7}, {%8,%9}, {%0,%1,%2,%3};"
        : "+f"(c[0]), "+f"(c[1]), "+f"(c[2]), "+f"(c[3])
        : "r"(a0), "r"(a1), "r"(a2), "r"(a3), "r"(b0), "r"(b1));
}

#define SA 20
#define SB 136

__global__ __launch_bounds__(256, 2)
void mma_gemm_kernel(const float* __restrict__ A, const float* __restrict__ Bm,
                     float* __restrict__ C, int ldc,
                     const float* __restrict__ bias, float bscale) {
    const int K = 256;
    __shared__ unsigned As[2][128 * SA];   // 20480 B
    __shared__ unsigned Bs[2][16 * SB];    // 17408 B

    const int tid  = threadIdx.x;
    const int wid  = tid >> 5;
    const int lane = tid & 31;
    const int g    = lane >> 2;   // groupID 0..7
    const int t    = lane & 3;    // thread-in-group 0..3
    const int wm   = wid >> 2;    // 0..1 (64 rows)
    const int wn   = wid & 3;     // 0..3 (32 cols)

    const float* Ap = A + (size_t)blockIdx.y * 128 * K;
    const float* Bp = Bm + blockIdx.x * 128;

    // loader mapping
    const int ar  = tid >> 2;          // A row 0..63 (and +64)
    const int ac  = (tid & 3) << 2;    // A col 0,4,8,12
    const int bkr = wid;               // B k-row 0..7 (and +8)
    const int bnc = lane << 2;         // B col 0..124

    float acc[4][4][4];
#pragma unroll
    for (int i = 0; i < 4; ++i)
#pragma unroll
        for (int j = 0; j < 4; ++j)
#pragma unroll
            for (int r = 0; r < 4; ++r) acc[i][j][r] = 0.f;

    // prologue: stage 0
    float4 av0 = *(const float4*)(Ap + (size_t)ar * K + ac);
    float4 av1 = *(const float4*)(Ap + (size_t)(ar + 64) * K + ac);
    float4 bv0 = *(const float4*)(Bp + (size_t)bkr * 256 + bnc);
    float4 bv1 = *(const float4*)(Bp + (size_t)(bkr + 8) * 256 + bnc);
    *(uint4*)&As[0][ar * SA + ac]        = cvt_tf32x4(av0);
    *(uint4*)&As[0][(ar + 64) * SA + ac] = cvt_tf32x4(av1);
    *(uint4*)&Bs[0][bkr * SB + bnc]      = cvt_tf32x4(bv0);
    *(uint4*)&Bs[0][(bkr + 8) * SB + bnc]= cvt_tf32x4(bv1);
    __syncthreads();

    for (int s = 0; s < 16; ++s) {
        const int buf = s & 1;
        if (s < 15) {
            const int k0 = (s + 1) * 16;
            av0 = *(const float4*)(Ap + (size_t)ar * K + k0 + ac);
            av1 = *(const float4*)(Ap + (size_t)(ar + 64) * K + k0 + ac);
            bv0 = *(const float4*)(Bp + (size_t)(k0 + bkr) * 256 + bnc);
            bv1 = *(const float4*)(Bp + (size_t)(k0 + bkr + 8) * 256 + bnc);
        }

#pragma unroll
        for (int ks = 0; ks < 2; ++ks) {
            const int krow = ks * 8 + t;
            unsigned bf0[4], bf1[4];
#pragma unroll
            for (int nt = 0; nt < 4; ++nt) {
                const int col = wn * 32 + nt * 8 + g;
                bf0[nt] = Bs[buf][krow * SB + col];
                bf1[nt] = Bs[buf][(krow + 4) * SB + col];
            }
#pragma unroll
            for (int mt = 0; mt < 4; ++mt) {
                const int row = wm * 64 + mt * 16 + g;
                unsigned a0 = As[buf][row * SA + krow];
                unsigned a1 = As[buf][(row + 8) * SA + krow];
                unsigned a2 = As[buf][row * SA + krow + 4];
                unsigned a3 = As[buf][(row + 8) * SA + krow + 4];
#pragma unroll
                for (int nt = 0; nt < 4; ++nt)
                    mma_tf32(acc[mt][nt], a0, a1, a2, a3, bf0[nt], bf1[nt]);
            }
        }

        if (s < 15) {
            const int nb = buf ^ 1;
            *(uint4*)&As[nb][ar * SA + ac]         = cvt_tf32x4(av0);
            *(uint4*)&As[nb][(ar + 64) * SA + ac]  = cvt_tf32x4(av1);
            *(uint4*)&Bs[nb][bkr * SB + bnc]       = cvt_tf32x4(bv0);
            *(uint4*)&Bs[nb][(bkr + 8) * SB + bnc] = cvt_tf32x4(bv1);
            __syncthreads();
        }
    }

    // epilogue
    const int rbase = blockIdx.y * 128 + wm * 64;
    const int cbase = blockIdx.x * 128 + wn * 32;
#pragma unroll
    for (int nt = 0; nt < 4; ++nt) {
        const int col = cbase + nt * 8 + 2 * t;
        float b0 = bias ? bias[col] * bscale : 0.f;
        float b1 = bias ? bias[col + 1] * bscale : 0.f;
#pragma unroll
        for (int mt = 0; mt < 4; ++mt) {
            const int row = rbase + mt * 16 + g;
            float2 v0 = make_float2(acc[mt][nt][0] + b0, acc[mt][nt][1] + b1);
            float2 v1 = make_float2(acc[mt][nt][2] + b0, acc[mt][nt][3] + b1);
            *(float2*)(C + (size_t)row * ldc + col)       = v0;
            *(float2*)(C + (size_t)(row + 8) * ldc + col) = v1;
        }
    }
}

// ---------------------------------------------------------------------------
// Gather-reduce: S[q,:] = sum_k relu(Q[b,idx_k,:] + P[q,:]) * dw_k
// ---------------------------------------------------------------------------
__global__ void gather_reduce_kernel(const float* __restrict__ P,
                                     const float* __restrict__ Q,
                                     const int* __restrict__ idx,
                                     const float* __restrict__ dw,
                                     float* __restrict__ S) {
    const int tid = threadIdx.x;
    const int q = blockIdx.x * 4 + (tid >> 6);
    const int l = tid & 63;
    const int b = q >> 13;

    const float4* P4 = (const float4*)P;
    const float4* Q4 = (const float4*)Q + (size_t)b * NB_ * 64;

    const float4 p = P4[(size_t)q * 64 + l];
    float4 acc = make_float4(0.f, 0.f, 0.f, 0.f);

#pragma unroll
    for (int k = 0; k < 8; ++k) {
        const int   j = idx[(size_t)q * 8 + k];
        const float w = dw[(size_t)q * 8 + k];
        const float4 v = Q4[(size_t)j * 64 + l];
        acc.x += fmaxf(v.x + p.x, 0.f) * w;
        acc.y += fmaxf(v.y + p.y, 0.f) * w;
        acc.z += fmaxf(v.z + p.z, 0.f) * w;
        acc.w += fmaxf(v.w + p.w, 0.f) * w;
    }
    ((float4*)S)[(size_t)q * 64 + l] = acc;
}

// ---------------------------------------------------------------------------
// Copy a_feats into out[..., 0:256] (out is [B, Na, 512])
// ---------------------------------------------------------------------------
__global__ void copy_a_kernel(const float4* __restrict__ af4, float4* __restrict__ out4) {
    const int i = blockIdx.x * blockDim.x + threadIdx.x;
    const int m = i >> 6;
    const int c = i & 63;
    out4[(size_t)m * 128 + c] = af4[i];
}

// ---------------------------------------------------------------------------
extern "C" void kernel_launch(void* const* d_in, const int* in_sizes, int n_in,
                              void* d_out, int out_size) {
    const float* af = (const float*)d_in[0];
    const float* bf = (const float*)d_in[1];
    const int*   ca = (const int*)d_in[2];
    const int*   cb = (const int*)d_in[3];
    const float* w1 = (const float*)d_in[4];
    const float* b1 = (const float*)d_in[5];
    const float* w2 = (const float*)d_in[6];
    const float* b2 = (const float*)d_in[7];
    float* out = (float*)d_out;

    float *P, *Q, *S, *WdT, *W1bT, *W2T, *dw;
    int* idx;
    cudaGetSymbolAddress((void**)&P,    g_P);
    cudaGetSymbolAddress((void**)&Q,    g_Q);
    cudaGetSymbolAddress((void**)&S,    g_S);
    cudaGetSymbolAddress((void**)&WdT,  g_WdT);
    cudaGetSymbolAddress((void**)&W1bT, g_W1bT);
    cudaGetSymbolAddress((void**)&W2T,  g_W2T);
    cudaGetSymbolAddress((void**)&idx,  g_idx);
    cudaGetSymbolAddress((void**)&dw,   g_dw);

    // 1. Weight prep (tiny)
    prep_w_kernel<<<256, 256>>>(w1, w2, WdT, W1bT, W2T);

    // 2. Exact top-8 kNN (one warp per query)
    knn_kernel<<<dim3(NA / 8, B_), 256>>>(ca, cb, idx, dw);

    // 3. P = af @ W1b^T + b1   [32768, 256]
    mma_gemm_kernel<<<dim3(2, (B_ * NA) / 128), 256>>>(af, W1bT, P, 256, b1, 1.f);

    // 4. Q = bf @ (W1a - W1b)^T  [32768, 256]
    mma_gemm_kernel<<<dim3(2, (B_ * NB_) / 128), 256>>>(bf, WdT, Q, 256, (const float*)nullptr, 0.f);

    // 5. S = sum_k relu(Q[idx_k] + P) * dw_k
    gather_reduce_kernel<<<(B_ * NA) / 4, 256>>>(P, Q, idx, dw, S);

    // 6. out[..., 256:512] = S @ W2^T + 8*b2   (strided epilogue, ldc=512)
    mma_gemm_kernel<<<dim3(2, (B_ * NA) / 128), 256>>>(S, W2T, out + 256, 512, b2, 8.f);

    // 7. out[..., 0:256] = a_feats
    copy_a_kernel<<<(B_ * NA * D_ / 4) / 256, 256>>>((const float4*)af, (float4*)out);
}

// round 6
// speedup vs baseline: 2.9362x; 2.7143x over previous
#include <cuda_runtime.h>
#include <cuda_bf16.h>
#include <math.h>

// Problem shape (fixed for this problem instance)
#define B_    4
#define NA    8192
#define NB_   8192
#define D_    256
#define TOPK  8
#define NCELL 512      // 8x8x8 grid of cells, cell side 16 (in //16 coords)

// ---------------------------------------------------------------------------
// Scratch (static device globals; no dynamic allocation allowed)
// ---------------------------------------------------------------------------
__device__ float g_P[B_ * NA * D_];        // af @ W1b^T + b1      [32768,256]
__device__ float g_Q[B_ * NB_ * D_];       // bf @ (W1a-W1b)^T     [32768,256]
__device__ float g_S[B_ * NA * D_];        // sum_k relu(Q+P)*dw   [32768,256]
__device__ float g_WdT[D_ * D_];           // (W1a-W1b)^T  [c,d]
__device__ float g_W1bT[D_ * D_];          // W1b^T        [c,d]
__device__ float g_W2T[D_ * D_];           // W2^T         [d,e]
__device__ int   g_idx[B_ * NA * TOPK];
__device__ float g_dw[B_ * NA * TOPK];

// spatial grid scratch
__device__ int      g_cellcnt[B_ * NCELL];
__device__ int      g_cellstart[B_ * (NCELL + 1)];
__device__ int      g_cellcur[B_ * NCELL];
__device__ uint2    g_pts[B_ * NB_];       // cell-sorted (packed coord, index)
__device__ unsigned g_cbp[B_ * NB_];       // packed //16 coords, original order

// ---------------------------------------------------------------------------
// Weight preprocessing
// ---------------------------------------------------------------------------
__global__ void prep_w_kernel(const float* __restrict__ w1,
                              const float* __restrict__ w2,
                              float* __restrict__ WdT,
                              float* __restrict__ W1bT,
                              float* __restrict__ W2T) {
    int i = blockIdx.x;
    int t = threadIdx.x;
    float a = w1[t * 512 + i];
    float b = w1[t * 512 + 256 + i];
    WdT[i * 256 + t]  = a - b;
    W1bT[i * 256 + t] = b;
    W2T[i * 256 + t]  = w2[t * 256 + i];
}

// ---------------------------------------------------------------------------
// Spatial grid build: zero -> histogram -> scan -> scatter
// ---------------------------------------------------------------------------
__global__ void zero_cnt_kernel(int* __restrict__ cnt) {
    cnt[blockIdx.x * blockDim.x + threadIdx.x] = 0;
}

__global__ void hist_kernel(const int* __restrict__ coords_b,
                            unsigned* __restrict__ cbp,
                            int* __restrict__ cnt) {
    const int i = blockIdx.x * blockDim.x + threadIdx.x;   // 0..B*NB-1
    const int b = i >> 13;
    const int* cb = coords_b + (size_t)i * 3;
    const unsigned x = ((unsigned)cb[0]) >> 4;
    const unsigned y = ((unsigned)cb[1]) >> 4;
    const unsigned z = ((unsigned)cb[2]) >> 4;
    cbp[i] = x | (y << 8) | (z << 16);
    const int cell = (int)(((x >> 4) << 6) | ((y >> 4) << 3) | (z >> 4));
    atomicAdd(&cnt[b * NCELL + cell], 1);
}

__global__ void scan_kernel(const int* __restrict__ cnt,
                            int* __restrict__ cellstart,
                            int* __restrict__ cur) {
    __shared__ int sc[NCELL];
    const int b = blockIdx.x, t = threadIdx.x;
    const int v = cnt[b * NCELL + t];
    sc[t] = v;
    __syncthreads();
    for (int off = 1; off < NCELL; off <<= 1) {
        int x = (t >= off) ? sc[t - off] : 0;
        __syncthreads();
        sc[t] += x;
        __syncthreads();
    }
    cellstart[b * (NCELL + 1) + t + 1] = sc[t];
    if (t == 0) cellstart[b * (NCELL + 1)] = 0;
    cur[b * NCELL + t] = sc[t] - v;   // exclusive
}

__global__ void scatter_kernel(const unsigned* __restrict__ cbp,
                               int* __restrict__ cur,
                               uint2* __restrict__ pts) {
    const int i = blockIdx.x * blockDim.x + threadIdx.x;
    const int b = i >> 13, j = i & 8191;
    const unsigned p = cbp[i];
    const int cell = (int)((((p >> 4) & 7u) << 6) | (((p >> 12) & 7u) << 3) | ((p >> 20) & 7u));
    const int pos = atomicAdd(&cur[b * NCELL + cell], 1);
    pts[(size_t)b * NB_ + pos] = make_uint2(p, (unsigned)j);
}

// ---------------------------------------------------------------------------
// kNN helpers
// ---------------------------------------------------------------------------
__device__ __forceinline__ void insert8(unsigned best[8], unsigned key) {
    if (key < best[7]) {
        best[7] = key;
#pragma unroll
        for (int t = 7; t > 0; --t) {
            unsigned lo = min(best[t - 1], best[t]);
            unsigned hi = max(best[t - 1], best[t]);
            best[t - 1] = lo;
            best[t]     = hi;
        }
    }
}

// 8-round pop-merge: afterwards lane r holds the r-th smallest key warpwide.
// Keys are unique (low 13 bits = candidate index), so pops are exact.
__device__ __forceinline__ unsigned merge8(unsigned best[8], int lane) {
    unsigned sel = 0;
#pragma unroll
    for (int r = 0; r < 8; ++r) {
        const unsigned v = best[0];
        const unsigned m = __reduce_min_sync(0xFFFFFFFFu, v);
        if (lane == r) sel = m;
        if (v == m) {
#pragma unroll
            for (int t = 0; t < 7; ++t) best[t] = best[t + 1];
            best[7] = 0xFFFFFFFFu;
        }
    }
    return sel;
}

// ---------------------------------------------------------------------------
// Grid kNN: one warp per query. Scan the 3^3 (clamped) cell neighborhood,
// then CERTIFY: if the 8th-best d2 could be beaten (or index-tied) by any
// point outside the neighborhood, fall back to an exact brute scan.
// key = (d2<<13)|j reproduces jax top_k lower-index tie-breaking exactly.
// ---------------------------------------------------------------------------
__global__ void knn_grid_kernel(const int* __restrict__ coords_a,
                                const unsigned* __restrict__ cbp,
                                const uint2* __restrict__ pts,
                                const int* __restrict__ cellstart,
                                int* __restrict__ idx_out,
                                float* __restrict__ dw_out) {
    const int b = blockIdx.y;
    const int warp = threadIdx.x >> 5;
    const int lane = threadIdx.x & 31;
    const int n = blockIdx.x * 8 + warp;

    const int* ca = coords_a + ((size_t)b * NA + n) * 3;
    const unsigned qx = ((unsigned)ca[0]) >> 4;
    const unsigned qy = ((unsigned)ca[1]) >> 4;
    const unsigned qz = ((unsigned)ca[2]) >> 4;
    const unsigned qp = qx | (qy << 8) | (qz << 16);

    const int cx = (int)(qx >> 4), cy = (int)(qy >> 4), cz = (int)(qz >> 4);
    const int x0 = max(cx - 1, 0), x1 = min(cx + 1, 7);
    const int y0 = max(cy - 1, 0), y1 = min(cy + 1, 7);
    const int z0 = max(cz - 1, 0), z1 = min(cz + 1, 7);

    const int sbase = b * (NCELL + 1);
    const uint2* ptsb = pts + (size_t)b * NB_;

    unsigned best[8];
#pragma unroll
    for (int t = 0; t < 8; ++t) best[t] = 0xFFFFFFFFu;

    for (int x = x0; x <= x1; ++x)
        for (int y = y0; y <= y1; ++y)
            for (int z = z0; z <= z1; ++z) {
                const int c = (x << 6) | (y << 3) | z;
                const int s = __ldg(&cellstart[sbase + c]);
                const int e = __ldg(&cellstart[sbase + c + 1]);
                for (int o = s + lane; o < e; o += 32) {
                    const uint2 pt = ptsb[o];
                    const unsigned ad = __vabsdiffu4(pt.x, qp);
                    const unsigned d2 = (unsigned)__dp4a((int)ad, (int)ad, 0);
                    insert8(best, (d2 << 13) | pt.y);
                }
            }

    unsigned sel = merge8(best, lane);

    // Certification: nearest possible OUTSIDE point (domain edges have no
    // points beyond them, so only interior boundaries constrain).
    const unsigned d2_8 = __shfl_sync(0xFFFFFFFFu, sel, 7) >> 13;
    int mo = 0x7FFFFFFF;
    if (x0 > 0) { int d = (int)qx - (16 * x0 - 1); mo = min(mo, d * d); }
    if (x1 < 7) { int d = 16 * (x1 + 1) - (int)qx; mo = min(mo, d * d); }
    if (y0 > 0) { int d = (int)qy - (16 * y0 - 1); mo = min(mo, d * d); }
    if (y1 < 7) { int d = 16 * (y1 + 1) - (int)qy; mo = min(mo, d * d); }
    if (z0 > 0) { int d = (int)qz - (16 * z0 - 1); mo = min(mo, d * d); }
    if (z1 < 7) { int d = 16 * (z1 + 1) - (int)qz; mo = min(mo, d * d); }

    if (d2_8 >= (unsigned)mo) {   // warp-uniform; vanishingly rare
#pragma unroll
        for (int t = 0; t < 8; ++t) best[t] = 0xFFFFFFFFu;
        const unsigned* cb = cbp + (size_t)b * NB_;
        for (int j = lane; j < NB_; j += 32) {
            const unsigned p = __ldg(&cb[j]);
            const unsigned ad = __vabsdiffu4(p, qp);
            const unsigned d2 = (unsigned)__dp4a((int)ad, (int)ad, 0);
            insert8(best, (d2 << 13) | (unsigned)j);
        }
        sel = merge8(best, lane);
    }

    if (lane < 8) {
        const int j = (int)(sel & 8191u);
        const float dist = sqrtf((float)(sel >> 13)) * (1.0f / 128.0f);
        const float dwv = 0.5f - fminf(dist, 0.5f);
        const size_t o = ((size_t)b * NA + n) * 8 + lane;
        idx_out[o] = j;
        dw_out[o]  = dwv;
    }
}

// ---------------------------------------------------------------------------
// TF32 tensor-core GEMM: C[M,256] = A[M,256] @ B[256,256] (+ bscale*bias)
// BM=BN=128, BK=16, 256 threads, 8 warps as 2x4 (warp tile 64x32).
// ---------------------------------------------------------------------------
__device__ __forceinline__ uint4 cvt_tf32x4(float4 v) {
    uint4 r;
    asm("cvt.rna.tf32.f32 %0, %1;" : "=r"(r.x) : "f"(v.x));
    asm("cvt.rna.tf32.f32 %0, %1;" : "=r"(r.y) : "f"(v.y));
    asm("cvt.rna.tf32.f32 %0, %1;" : "=r"(r.z) : "f"(v.z));
    asm("cvt.rna.tf32.f32 %0, %1;" : "=r"(r.w) : "f"(v.w));
    return r;
}

__device__ __forceinline__ void mma_tf32(float* c,
                                         unsigned a0, unsigned a1, unsigned a2, unsigned a3,
                                         unsigned b0, unsigned b1) {
    asm volatile(
        "mma.sync.aligned.m16n8k8.row.col.f32.tf32.tf32.f32 "
        "{%0,%1,%2,%3}, {%4,%5,%6,%7}, {%8,%9}, {%0,%1,%2,%3};"
        : "+f"(c[0]), "+f"(c[1]), "+f"(c[2]), "+f"(c[3])
        : "r"(a0), "r"(a1), "r"(a2), "r"(a3), "r"(b0), "r"(b1));
}

#define SA 20
#define SB 136

__global__ __launch_bounds__(256, 2)
void mma_gemm_kernel(const float* __restrict__ A, const float* __restrict__ Bm,
                     float* __restrict__ C, int ldc,
                     const float* __restrict__ bias, float bscale) {
    const int K = 256;
    __shared__ unsigned As[2][128 * SA];
    __shared__ unsigned Bs[2][16 * SB];

    const int tid  = threadIdx.x;
    const int wid  = tid >> 5;
    const int lane = tid & 31;
    const int g    = lane >> 2;
    const int t    = lane & 3;
    const int wm   = wid >> 2;
    const int wn   = wid & 3;

    const float* Ap = A + (size_t)blockIdx.y * 128 * K;
    const float* Bp = Bm + blockIdx.x * 128;

    const int ar  = tid >> 2;
    const int ac  = (tid & 3) << 2;
    const int bkr = wid;
    const int bnc = lane << 2;

    float acc[4][4][4];
#pragma unroll
    for (int i = 0; i < 4; ++i)
#pragma unroll
        for (int j = 0; j < 4; ++j)
#pragma unroll
            for (int r = 0; r < 4; ++r) acc[i][j][r] = 0.f;

    float4 av0 = *(const float4*)(Ap + (size_t)ar * K + ac);
    float4 av1 = *(const float4*)(Ap + (size_t)(ar + 64) * K + ac);
    float4 bv0 = *(const float4*)(Bp + (size_t)bkr * 256 + bnc);
    float4 bv1 = *(const float4*)(Bp + (size_t)(bkr + 8) * 256 + bnc);
    *(uint4*)&As[0][ar * SA + ac]         = cvt_tf32x4(av0);
    *(uint4*)&As[0][(ar + 64) * SA + ac]  = cvt_tf32x4(av1);
    *(uint4*)&Bs[0][bkr * SB + bnc]       = cvt_tf32x4(bv0);
    *(uint4*)&Bs[0][(bkr + 8) * SB + bnc] = cvt_tf32x4(bv1);
    __syncthreads();

    for (int s = 0; s < 16; ++s) {
        const int buf = s & 1;
        if (s < 15) {
            const int k0 = (s + 1) * 16;
            av0 = *(const float4*)(Ap + (size_t)ar * K + k0 + ac);
            av1 = *(const float4*)(Ap + (size_t)(ar + 64) * K + k0 + ac);
            bv0 = *(const float4*)(Bp + (size_t)(k0 + bkr) * 256 + bnc);
            bv1 = *(const float4*)(Bp + (size_t)(k0 + bkr + 8) * 256 + bnc);
        }

#pragma unroll
        for (int ks = 0; ks < 2; ++ks) {
            const int krow = ks * 8 + t;
            unsigned bf0[4], bf1[4];
#pragma unroll
            for (int nt = 0; nt < 4; ++nt) {
                const int col = wn * 32 + nt * 8 + g;
                bf0[nt] = Bs[buf][krow * SB + col];
                bf1[nt] = Bs[buf][(krow + 4) * SB + col];
            }
#pragma unroll
            for (int mt = 0; mt < 4; ++mt) {
                const int row = wm * 64 + mt * 16 + g;
                unsigned a0 = As[buf][row * SA + krow];
                unsigned a1 = As[buf][(row + 8) * SA + krow];
                unsigned a2 = As[buf][row * SA + krow + 4];
                unsigned a3 = As[buf][(row + 8) * SA + krow + 4];
#pragma unroll
                for (int nt = 0; nt < 4; ++nt)
                    mma_tf32(acc[mt][nt], a0, a1, a2, a3, bf0[nt], bf1[nt]);
            }
        }

        if (s < 15) {
            const int nb = buf ^ 1;
            *(uint4*)&As[nb][ar * SA + ac]         = cvt_tf32x4(av0);
            *(uint4*)&As[nb][(ar + 64) * SA + ac]  = cvt_tf32x4(av1);
            *(uint4*)&Bs[nb][bkr * SB + bnc]       = cvt_tf32x4(bv0);
            *(uint4*)&Bs[nb][(bkr + 8) * SB + bnc] = cvt_tf32x4(bv1);
            __syncthreads();
        }
    }

    const int rbase = blockIdx.y * 128 + wm * 64;
    const int cbase = blockIdx.x * 128 + wn * 32;
#pragma unroll
    for (int nt = 0; nt < 4; ++nt) {
        const int col = cbase + nt * 8 + 2 * t;
        float b0 = bias ? bias[col] * bscale : 0.f;
        float b1 = bias ? bias[col + 1] * bscale : 0.f;
#pragma unroll
        for (int mt = 0; mt < 4; ++mt) {
            const int row = rbase + mt * 16 + g;
            float2 v0 = make_float2(acc[mt][nt][0] + b0, acc[mt][nt][1] + b1);
            float2 v1 = make_float2(acc[mt][nt][2] + b0, acc[mt][nt][3] + b1);
            *(float2*)(C + (size_t)row * ldc + col)       = v0;
            *(float2*)(C + (size_t)(row + 8) * ldc + col) = v1;
        }
    }
}

// ---------------------------------------------------------------------------
// Gather-reduce + a_feats copy:
//   S[q,:]            = sum_k relu(Q[b,idx_k,:] + P[q,:]) * dw_k
//   out[q, 0:256]     = af[q,:]
// 64 threads per query (float4 each), 4 queries per 256-thread block.
// ---------------------------------------------------------------------------
__global__ void gather_reduce_copy_kernel(const float* __restrict__ P,
                                          const float* __restrict__ Q,
                                          const int* __restrict__ idx,
                                          const float* __restrict__ dw,
                                          const float* __restrict__ af,
                                          float* __restrict__ out,
                                          float* __restrict__ S) {
    const int tid = threadIdx.x;
    const int q = blockIdx.x * 4 + (tid >> 6);
    const int l = tid & 63;
    const int b = q >> 13;

    // copy a_feats into out[..., 0:256]  (out row stride = 128 float4)
    ((float4*)out)[(size_t)q * 128 + l] = ((const float4*)af)[(size_t)q * 64 + l];

    const float4* P4 = (const float4*)P;
    const float4* Q4 = (const float4*)Q + (size_t)b * NB_ * 64;

    const float4 p = P4[(size_t)q * 64 + l];
    float4 acc = make_float4(0.f, 0.f, 0.f, 0.f);

#pragma unroll
    for (int k = 0; k < 8; ++k) {
        const int   j = idx[(size_t)q * 8 + k];
        const float w = dw[(size_t)q * 8 + k];
        const float4 v = Q4[(size_t)j * 64 + l];
        acc.x += fmaxf(v.x + p.x, 0.f) * w;
        acc.y += fmaxf(v.y + p.y, 0.f) * w;
        acc.z += fmaxf(v.z + p.z, 0.f) * w;
        acc.w += fmaxf(v.w + p.w, 0.f) * w;
    }
    ((float4*)S)[(size_t)q * 64 + l] = acc;
}

// ---------------------------------------------------------------------------
extern "C" void kernel_launch(void* const* d_in, const int* in_sizes, int n_in,
                              void* d_out, int out_size) {
    const float* af = (const float*)d_in[0];
    const float* bf = (const float*)d_in[1];
    const int*   ca = (const int*)d_in[2];
    const int*   cb = (const int*)d_in[3];
    const float* w1 = (const float*)d_in[4];
    const float* b1 = (const float*)d_in[5];
    const float* w2 = (const float*)d_in[6];
    const float* b2 = (const float*)d_in[7];
    float* out = (float*)d_out;

    float *P, *Q, *S, *WdT, *W1bT, *W2T, *dw;
    int *idx, *ccnt, *cstart, *ccur;
    uint2* pts;
    unsigned* cbp;
    cudaGetSymbolAddress((void**)&P,      g_P);
    cudaGetSymbolAddress((void**)&Q,      g_Q);
    cudaGetSymbolAddress((void**)&S,      g_S);
    cudaGetSymbolAddress((void**)&WdT,    g_WdT);
    cudaGetSymbolAddress((void**)&W1bT,   g_W1bT);
    cudaGetSymbolAddress((void**)&W2T,    g_W2T);
    cudaGetSymbolAddress((void**)&idx,    g_idx);
    cudaGetSymbolAddress((void**)&dw,     g_dw);
    cudaGetSymbolAddress((void**)&ccnt,   g_cellcnt);
    cudaGetSymbolAddress((void**)&cstart, g_cellstart);
    cudaGetSymbolAddress((void**)&ccur,   g_cellcur);
    cudaGetSymbolAddress((void**)&pts,    g_pts);
    cudaGetSymbolAddress((void**)&cbp,    g_cbp);

    // 1. spatial grid build
    zero_cnt_kernel<<<B_, NCELL>>>(ccnt);
    hist_kernel<<<(B_ * NB_) / 256, 256>>>(cb, cbp, ccnt);
    scan_kernel<<<B_, NCELL>>>(ccnt, cstart, ccur);
    scatter_kernel<<<(B_ * NB_) / 256, 256>>>(cbp, ccur, pts);

    // 2. exact certified grid kNN
    knn_grid_kernel<<<dim3(NA / 8, B_), 256>>>(ca, cbp, pts, cstart, idx, dw);

    // 3. weight prep
    prep_w_kernel<<<256, 256>>>(w1, w2, WdT, W1bT, W2T);

    // 4. P = af @ W1b^T + b1
    mma_gemm_kernel<<<dim3(2, (B_ * NA) / 128), 256>>>(af, W1bT, P, 256, b1, 1.f);

    // 5. Q = bf @ (W1a - W1b)^T
    mma_gemm_kernel<<<dim3(2, (B_ * NB_) / 128), 256>>>(bf, WdT, Q, 256, (const float*)nullptr, 0.f);

    // 6. S = sum_k relu(Q[idx_k] + P) * dw_k ; out[...,0:256] = af
    gather_reduce_copy_kernel<<<(B_ * NA) / 4, 256>>>(P, Q, idx, dw, af, out, S);

    // 7. out[..., 256:512] = S @ W2^T + 8*b2
    mma_gemm_kernel<<<dim3(2, (B_ * NA) / 128), 256>>>(S, W2T, out + 256, 512, b2, 8.f);
}